// round 1
// baseline (speedup 1.0000x reference)
#include <cuda_runtime.h>
#include <math.h>

#define B_   64
#define N_   512
#define D_   1024

// Scratch (device globals: no allocation allowed in kernel_launch)
__device__ float g_tq[B_ * D_];        // query @ Ws        (64, 1024)
__device__ float g_logits[B_ * N_];    // pre-softmax       (64, 512)
__device__ float g_weights[B_ * N_];   // softmax weights   (64, 512)

// ---------------------------------------------------------------------------
// Kernel 1: tq = query @ Ws   (64,1024) @ (1024,1024)
// grid (16 a-tiles, 4 b-tiles), 256 threads. Each block: 16 b x 64 a, full K.
// ---------------------------------------------------------------------------
__global__ void tq_kernel(const float* __restrict__ query,
                          const float* __restrict__ Ws)
{
    __shared__ float Qs[16][32];
    __shared__ float Wss[32][64];
    const int tid     = threadIdx.x;
    const int a_local = tid & 63;
    const int br      = tid >> 6;          // 0..3
    const int a0      = blockIdx.x * 64;
    const int b0      = blockIdx.y * 16;

    float acc[4] = {0.f, 0.f, 0.f, 0.f};

    for (int k0 = 0; k0 < D_; k0 += 32) {
        #pragma unroll
        for (int i = 0; i < 2; i++) {
            int idx = tid + i * 256;
            int bq = idx >> 5, kq = idx & 31;
            Qs[bq][kq] = query[(b0 + bq) * D_ + k0 + kq];
        }
        #pragma unroll
        for (int i = 0; i < 8; i++) {
            int idx = tid + i * 256;
            int kw = idx >> 6, aw = idx & 63;
            Wss[kw][aw] = Ws[(k0 + kw) * D_ + a0 + aw];
        }
        __syncthreads();
        #pragma unroll
        for (int kk = 0; kk < 32; kk++) {
            float wv = Wss[kk][a_local];
            #pragma unroll
            for (int q = 0; q < 4; q++)
                acc[q] += Qs[br + q * 4][kk] * wv;
        }
        __syncthreads();
    }
    #pragma unroll
    for (int q = 0; q < 4; q++)
        g_tq[(b0 + br + q * 4) * D_ + a0 + a_local] = acc[q];
}

// ---------------------------------------------------------------------------
// Kernel 2 (dominant): logits[b,n] = tanh(M[b,n,:] @ Wh + tq[b,:]) @ v
// Fused: never materializes h (B,N,1024). Register-tiled SIMT fp32 GEMM.
// 128-row tile per block (each tile sits inside one batch since N=512 % 128 == 0),
// loops the 8 column tiles of AD; per column tile the tanh*v epilogue reduces
// into per-row partial logits kept in registers.
// grid 256 blocks, 256 threads (16x16), 8x8 micro-tile, BK=16.
// ---------------------------------------------------------------------------
#define BM 128
#define BN 128
#define BK 16
#define TM 8
#define TN 8

__global__ __launch_bounds__(256, 2)
void logits_kernel(const float* __restrict__ M,
                   const float* __restrict__ Wh,
                   const float* __restrict__ v)
{
    __shared__ float As[BK][BM + 4];   // A transposed (k-major), +4 pad: f4-aligned, low conflict
    __shared__ float Bs[BK][BN];
    __shared__ float red[BM];

    const int tid  = threadIdx.x;
    const int tx   = tid & 15;
    const int ty   = tid >> 4;
    const int row0 = blockIdx.x * BM;   // flattened (b*N + n) row tile
    const int b    = row0 >> 9;         // N_ = 512

    if (tid < BM) red[tid] = 0.f;

    float part[TM];
    #pragma unroll
    for (int i = 0; i < TM; i++) part[i] = 0.f;

    for (int c0 = 0; c0 < D_; c0 += BN) {
        float acc[TM][TN];
        #pragma unroll
        for (int i = 0; i < TM; i++)
            #pragma unroll
            for (int j = 0; j < TN; j++) acc[i][j] = 0.f;

        for (int k0 = 0; k0 < D_; k0 += BK) {
            // Stage A tile (128 rows x 16 k), transposed into smem
            #pragma unroll
            for (int i = 0; i < 8; i++) {
                int idx = tid + i * 256;
                int r = idx >> 4, c = idx & 15;
                As[c][r] = M[(row0 + r) * D_ + k0 + c];
            }
            // Stage B tile (16 k x 128 cols)
            #pragma unroll
            for (int i = 0; i < 8; i++) {
                int idx = tid + i * 256;
                int kr = idx >> 7, n = idx & 127;
                Bs[kr][n] = Wh[(k0 + kr) * D_ + c0 + n];
            }
            __syncthreads();
            #pragma unroll
            for (int kk = 0; kk < BK; kk++) {
                float4 a0v = *(const float4*)&As[kk][ty * 8];
                float4 a1v = *(const float4*)&As[kk][ty * 8 + 4];
                float4 b0v = *(const float4*)&Bs[kk][tx * 8];
                float4 b1v = *(const float4*)&Bs[kk][tx * 8 + 4];
                float a[TM] = {a0v.x, a0v.y, a0v.z, a0v.w, a1v.x, a1v.y, a1v.z, a1v.w};
                float bb[TN] = {b0v.x, b0v.y, b0v.z, b0v.w, b1v.x, b1v.y, b1v.z, b1v.w};
                #pragma unroll
                for (int i = 0; i < TM; i++)
                    #pragma unroll
                    for (int j = 0; j < TN; j++)
                        acc[i][j] += a[i] * bb[j];
            }
            __syncthreads();
        }

        // Epilogue for this column tile: tanh(x + tq) * v, reduce over columns
        #pragma unroll
        for (int j = 0; j < TN; j++) {
            int col   = c0 + tx * 8 + j;
            float tad = g_tq[b * D_ + col];   // broadcast within warp (L1)
            float vv  = v[col];
            #pragma unroll
            for (int i = 0; i < TM; i++)
                part[i] += tanhf(acc[i][j] + tad) * vv;
        }
    }

    // Cross-thread (tx) reduction of per-row partials via smem atomics
    __syncthreads();
    #pragma unroll
    for (int i = 0; i < TM; i++)
        atomicAdd(&red[ty * 8 + i], part[i]);
    __syncthreads();
    if (tid < BM)
        g_logits[row0 + tid] = red[tid];
}

// ---------------------------------------------------------------------------
// Kernel 3: masked softmax over N per batch (handles all-masked rows)
// ---------------------------------------------------------------------------
__global__ void softmax_kernel(const int* __restrict__ mask)
{
    __shared__ float sm[N_];
    const int b = blockIdx.x;
    const int t = threadIdx.x;   // 512 threads

    const int   mk = mask[b * N_ + t];
    const float l  = g_logits[b * N_ + t];

    int any = __syncthreads_or(mk != 0);
    if (!any) {                      // uniform branch: whole row masked -> weights 0
        g_weights[b * N_ + t] = 0.f;
        return;
    }
    float x = (mk != 0) ? l : -1e30f;

    sm[t] = x;
    __syncthreads();
    #pragma unroll
    for (int s = 256; s > 0; s >>= 1) {
        if (t < s) sm[t] = fmaxf(sm[t], sm[t + s]);
        __syncthreads();
    }
    float mx = sm[0];
    __syncthreads();

    float e = expf(x - mx);          // masked lanes underflow to exactly 0
    sm[t] = e;
    __syncthreads();
    #pragma unroll
    for (int s = 256; s > 0; s >>= 1) {
        if (t < s) sm[t] += sm[t + s];
        __syncthreads();
    }
    g_weights[b * N_ + t] = e / sm[0];
}

// ---------------------------------------------------------------------------
// Kernel 4: context[b,:] = weights[b,:] @ M[b,:,:]   (DRAM-bound: 128 MB read)
// grid (8 d-tiles, 64 b), 128 threads; thread owns one d, loops n.
// ---------------------------------------------------------------------------
__global__ void context_kernel(const float* __restrict__ M,
                               float* __restrict__ out)
{
    __shared__ float ws[N_];
    const int b = blockIdx.y;
    const int d = blockIdx.x * 128 + threadIdx.x;
    for (int i = threadIdx.x; i < N_; i += 128)
        ws[i] = g_weights[b * N_ + i];
    __syncthreads();

    const float* Mb = M + (size_t)b * N_ * D_ + d;
    float acc = 0.f;
    #pragma unroll 8
    for (int n = 0; n < N_; n++)
        acc += ws[n] * Mb[(size_t)n * D_];
    out[b * D_ + d] = acc;
}

// ---------------------------------------------------------------------------
extern "C" void kernel_launch(void* const* d_in, const int* in_sizes, int n_in,
                              void* d_out, int out_size)
{
    const float* M     = (const float*)d_in[0];  // (64, 512, 1024)
    const int*   mask  = (const int*)  d_in[1];  // (64, 512)
    const float* query = (const float*)d_in[2];  // (64, 1024)
    const float* Wh    = (const float*)d_in[3];  // (1024, 1024)
    const float* Ws    = (const float*)d_in[4];  // (1024, 1024)
    const float* v     = (const float*)d_in[5];  // (1024, 1)
    float* out = (float*)d_out;                  // (64, 1024)

    tq_kernel<<<dim3(16, 4), 256>>>(query, Ws);
    logits_kernel<<<(B_ * N_) / BM, 256>>>(M, Wh, v);
    softmax_kernel<<<B_, N_>>>(mask);
    context_kernel<<<dim3(D_ / 128, B_), 128>>>(M, out);
}

// round 3
// speedup vs baseline: 3.5738x; 3.5738x over previous
#include <cuda_runtime.h>
#include <cstdint>
#include <math.h>

#define B_   64
#define N_   512
#define D_   1024

// Scratch (device globals: no allocation allowed)
__device__ float g_tq[B_ * N_ * 0 + B_ * D_];
__device__ float g_logits[B_ * N_];
__device__ float g_weights[B_ * N_];
__device__ float g_WhT[D_ * D_];   // Wh transposed (c,k), tf32-rounded (rna)

// ---------------------------------------------------------------------------
// helpers
// ---------------------------------------------------------------------------
__device__ __forceinline__ uint32_t smem_u32(const void* p) {
    uint32_t a;
    asm("{ .reg .u64 t; cvta.to.shared.u64 t, %1; cvt.u32.u64 %0, t; }" : "=r"(a) : "l"(p));
    return a;
}
__device__ __forceinline__ float ftf32(float f) {
    float o;
    asm("cvt.rna.tf32.f32 %0, %1;" : "=f"(o) : "f"(f));
    return o;
}
__device__ __forceinline__ float tanh_fast(float x) {
    float t;
    asm("tanh.approx.f32 %0, %1;" : "=f"(t) : "f"(x));
    return t;
}
__device__ __forceinline__ void cp16(uint32_t dst, const void* src) {
    asm volatile("cp.async.cg.shared.global [%0], [%1], 16;" :: "r"(dst), "l"(src));
}
#define CP_COMMIT() asm volatile("cp.async.commit_group;" ::: "memory")
#define CP_WAIT1()  asm volatile("cp.async.wait_group 1;" ::: "memory")
#define CP_WAIT0()  asm volatile("cp.async.wait_group 0;" ::: "memory")

__device__ __forceinline__ void ldsm4(uint32_t& r0, uint32_t& r1, uint32_t& r2, uint32_t& r3,
                                      uint32_t addr) {
    asm volatile("ldmatrix.sync.aligned.m8n8.x4.shared.b16 {%0,%1,%2,%3}, [%4];"
                 : "=r"(r0), "=r"(r1), "=r"(r2), "=r"(r3) : "r"(addr));
}
__device__ __forceinline__ void mma_frag(float* d, const uint32_t* a, const uint32_t* b) {
    asm volatile("mma.sync.aligned.m16n8k8.row.col.f32.tf32.tf32.f32 "
                 "{%0,%1,%2,%3}, {%4,%5,%6,%7}, {%8,%9}, {%0,%1,%2,%3};"
                 : "+f"(d[0]), "+f"(d[1]), "+f"(d[2]), "+f"(d[3])
                 : "r"(a[0]), "r"(a[1]), "r"(a[2]), "r"(a[3]), "r"(b[0]), "r"(b[1]));
}

// ---------------------------------------------------------------------------
// Kernel 1: tq = query @ Ws   (small fp32 SIMT)
// ---------------------------------------------------------------------------
__global__ void tq_kernel(const float* __restrict__ query,
                          const float* __restrict__ Ws)
{
    __shared__ float Qs[16][32];
    __shared__ float Wss[32][64];
    const int tid     = threadIdx.x;
    const int a_local = tid & 63;
    const int br      = tid >> 6;
    const int a0      = blockIdx.x * 64;
    const int b0      = blockIdx.y * 16;

    float acc[4] = {0.f, 0.f, 0.f, 0.f};
    for (int k0 = 0; k0 < D_; k0 += 32) {
        #pragma unroll
        for (int i = 0; i < 2; i++) {
            int idx = tid + i * 256;
            Qs[idx >> 5][idx & 31] = query[(b0 + (idx >> 5)) * D_ + k0 + (idx & 31)];
        }
        #pragma unroll
        for (int i = 0; i < 8; i++) {
            int idx = tid + i * 256;
            Wss[idx >> 6][idx & 63] = Ws[(k0 + (idx >> 6)) * D_ + a0 + (idx & 63)];
        }
        __syncthreads();
        #pragma unroll
        for (int kk = 0; kk < 32; kk++) {
            float wv = Wss[kk][a_local];
            #pragma unroll
            for (int q = 0; q < 4; q++) acc[q] += Qs[br + q * 4][kk] * wv;
        }
        __syncthreads();
    }
    #pragma unroll
    for (int q = 0; q < 4; q++)
        g_tq[(b0 + br + q * 4) * D_ + a0 + a_local] = acc[q];
}

// ---------------------------------------------------------------------------
// Kernel 2: WhT[c][k] = round_tf32(Wh[k][c])
// ---------------------------------------------------------------------------
__global__ void transpose_wh(const float* __restrict__ Wh)
{
    __shared__ float t[32][33];
    const int k0 = blockIdx.y * 32, c0 = blockIdx.x * 32;
    const int tx = threadIdx.x, ty = threadIdx.y;
    for (int i = ty; i < 32; i += 8)
        t[i][tx] = Wh[(size_t)(k0 + i) * D_ + c0 + tx];
    __syncthreads();
    for (int i = ty; i < 32; i += 8)
        g_WhT[(size_t)(c0 + i) * D_ + k0 + tx] = ftf32(t[tx][i]);
}

// ---------------------------------------------------------------------------
// Kernel 3 (dominant): tf32 mma.sync GEMM + fused tanh·v epilogue
//   logits[r] = sum_c tanh( (M@Wh)[r,c] + tq[b,c] ) * v[c]
// CTA: 128 rows, loops 8 column tiles of 128. 8 warps (2 m x 4 n), warp tile
// 64x32. cp.async 2-stage double buffering, BK=32, ldmatrix fragments.
// ---------------------------------------------------------------------------
#define ROWB  144                 // bytes per smem row (32 floats + 16B pad)
#define SA0   0
#define SB0   18432
#define SA1   36864
#define SB1   55296
#define SRED  73728
#define SMTOT (SRED + 512)

__device__ __forceinline__ void stage_tile(uint32_t sdst, const float* __restrict__ src0)
{
    const int tid = threadIdx.x;
    #pragma unroll
    for (int i = 0; i < 4; i++) {
        int idx = tid + i * 256;
        int r = idx >> 3, c = idx & 7;
        cp16(sdst + r * ROWB + c * 16, src0 + (size_t)r * D_ + c * 4);
    }
}

__global__ __launch_bounds__(256, 2)
void logits_mma(const float* __restrict__ M, const float* __restrict__ v)
{
    extern __shared__ char smem[];
    const uint32_t sb = smem_u32(smem);
    float* red = (float*)(smem + SRED);

    const int tid  = threadIdx.x;
    const int lane = tid & 31;
    const int wid  = tid >> 5;
    const int wm   = wid & 1;          // m block (2 x 64 rows)
    const int wn   = wid >> 1;         // n block (4 x 32 cols)
    const int g    = lane >> 2;        // group id
    const int tg   = lane & 3;         // thread in group
    const int rr   = lane & 7;         // ldmatrix row supplier
    const int j    = lane >> 3;        // ldmatrix matrix id

    const int row0 = blockIdx.x * 128;
    const int b    = row0 >> 9;

    if (tid < 128) red[tid] = 0.f;

    float part[8];
    #pragma unroll
    for (int i = 0; i < 8; i++) part[i] = 0.f;

    // precomputed ldmatrix smem offsets (within a buffer)
    const uint32_t a_off = (uint32_t)((wm * 64 + rr + (j & 1) * 8) * ROWB + (j >> 1) * 16);
    const uint32_t b_off = (uint32_t)((wn * 32 + rr + (j >> 1) * 8) * ROWB + (j & 1) * 16);

    for (int c0 = 0; c0 < D_; c0 += 128) {
        const float* Abase = M + (size_t)row0 * D_;
        const float* Bbase = g_WhT + (size_t)c0 * D_;

        float acc[4][4][4];
        #pragma unroll
        for (int mi = 0; mi < 4; mi++)
            #pragma unroll
            for (int ni = 0; ni < 4; ni++)
                #pragma unroll
                for (int q = 0; q < 4; q++) acc[mi][ni][q] = 0.f;

        // prologue: stage chunks 0,1
        stage_tile(sb + SA0, Abase + 0);
        stage_tile(sb + SB0, Bbase + 0);
        CP_COMMIT();
        stage_tile(sb + SA1, Abase + 32);
        stage_tile(sb + SB1, Bbase + 32);
        CP_COMMIT();

        for (int kt = 0; kt < 32; kt++) {
            if (kt == 31) CP_WAIT0(); else CP_WAIT1();
            __syncthreads();

            const uint32_t sA = sb + ((kt & 1) ? SA1 : SA0);
            const uint32_t sB = sb + ((kt & 1) ? SB1 : SB0);

            #pragma unroll
            for (int ks = 0; ks < 4; ks++) {
                uint32_t a[4][4];
                #pragma unroll
                for (int mi = 0; mi < 4; mi++)
                    ldsm4(a[mi][0], a[mi][1], a[mi][2], a[mi][3],
                          sA + a_off + mi * (16 * ROWB) + ks * 32);
                uint32_t bf[4][2];
                #pragma unroll
                for (int np = 0; np < 2; np++) {
                    uint32_t r0, r1, r2, r3;
                    ldsm4(r0, r1, r2, r3, sB + b_off + np * (16 * ROWB) + ks * 32);
                    bf[np * 2 + 0][0] = r0; bf[np * 2 + 0][1] = r1;
                    bf[np * 2 + 1][0] = r2; bf[np * 2 + 1][1] = r3;
                }
                #pragma unroll
                for (int mi = 0; mi < 4; mi++)
                    #pragma unroll
                    for (int ni = 0; ni < 4; ni++)
                        mma_frag(acc[mi][ni], a[mi], bf[ni]);
            }
            __syncthreads();
            if (kt + 2 < 32) {
                const uint32_t dA = sb + ((kt & 1) ? SA1 : SA0);
                const uint32_t dB = sb + ((kt & 1) ? SB1 : SB0);
                stage_tile(dA, Abase + (kt + 2) * 32);
                stage_tile(dB, Bbase + (kt + 2) * 32);
                CP_COMMIT();
            } else {
                CP_COMMIT();   // keep group counting uniform
            }
        }

        // fused epilogue for this column tile
        #pragma unroll
        for (int ni = 0; ni < 4; ni++) {
            const int cg = c0 + wn * 32 + ni * 8 + tg * 2;
            const float tq0 = __ldg(&g_tq[b * D_ + cg]);
            const float tq1 = __ldg(&g_tq[b * D_ + cg + 1]);
            const float v0  = __ldg(&v[cg]);
            const float v1  = __ldg(&v[cg + 1]);
            #pragma unroll
            for (int mi = 0; mi < 4; mi++) {
                part[2 * mi]     += tanh_fast(acc[mi][ni][0] + tq0) * v0
                                  + tanh_fast(acc[mi][ni][1] + tq1) * v1;
                part[2 * mi + 1] += tanh_fast(acc[mi][ni][2] + tq0) * v0
                                  + tanh_fast(acc[mi][ni][3] + tq1) * v1;
            }
        }
        __syncthreads();   // before restaging buffers next c0 iter
    }

    // reduce partials: lanes tg=0..3 hold disjoint cols of same rows
    #pragma unroll
    for (int i = 0; i < 8; i++) {
        float p = part[i];
        p += __shfl_xor_sync(0xFFFFFFFFu, p, 1);
        p += __shfl_xor_sync(0xFFFFFFFFu, p, 2);
        if (tg == 0) {
            int row = wm * 64 + (i >> 1) * 16 + (i & 1) * 8 + g;
            atomicAdd(&red[row], p);
        }
    }
    __syncthreads();
    if (tid < 128) g_logits[row0 + tid] = red[tid];
}

// ---------------------------------------------------------------------------
// Kernel 4: masked softmax per batch row
// ---------------------------------------------------------------------------
__global__ void softmax_kernel(const int* __restrict__ mask)
{
    __shared__ float sm[N_];
    const int b = blockIdx.x;
    const int t = threadIdx.x;

    const int   mk = mask[b * N_ + t];
    const float l  = g_logits[b * N_ + t];

    int any = __syncthreads_or(mk != 0);
    if (!any) {
        g_weights[b * N_ + t] = 0.f;
        return;
    }
    float x = (mk != 0) ? l : -1e30f;

    sm[t] = x;
    __syncthreads();
    #pragma unroll
    for (int s = 256; s > 0; s >>= 1) {
        if (t < s) sm[t] = fmaxf(sm[t], sm[t + s]);
        __syncthreads();
    }
    float mx = sm[0];
    __syncthreads();

    float e = expf(x - mx);
    sm[t] = e;
    __syncthreads();
    #pragma unroll
    for (int s = 256; s > 0; s >>= 1) {
        if (t < s) sm[t] += sm[t + s];
        __syncthreads();
    }
    g_weights[b * N_ + t] = e / sm[0];
}

// ---------------------------------------------------------------------------
// Kernel 5: context[b,:] = weights[b,:] @ M[b,:,:]  (DRAM-bound)
// ---------------------------------------------------------------------------
__global__ __launch_bounds__(256, 4)
void context_kernel(const float* __restrict__ M, float* __restrict__ out)
{
    __shared__ float ws[N_];
    const int b = blockIdx.y;
    const int d = blockIdx.x * 256 + threadIdx.x;
    for (int i = threadIdx.x; i < N_; i += 256)
        ws[i] = g_weights[b * N_ + i];
    __syncthreads();

    const float* Mb = M + (size_t)b * N_ * D_ + d;
    float a0 = 0.f, a1 = 0.f, a2 = 0.f, a3 = 0.f;
    #pragma unroll 4
    for (int n = 0; n < N_; n += 4) {
        a0 += ws[n + 0] * Mb[(size_t)(n + 0) * D_];
        a1 += ws[n + 1] * Mb[(size_t)(n + 1) * D_];
        a2 += ws[n + 2] * Mb[(size_t)(n + 2) * D_];
        a3 += ws[n + 3] * Mb[(size_t)(n + 3) * D_];
    }
    out[b * D_ + d] = (a0 + a1) + (a2 + a3);
}

// ---------------------------------------------------------------------------
extern "C" void kernel_launch(void* const* d_in, const int* in_sizes, int n_in,
                              void* d_out, int out_size)
{
    const float* M     = (const float*)d_in[0];  // (64, 512, 1024)
    const int*   mask  = (const int*)  d_in[1];  // (64, 512)
    const float* query = (const float*)d_in[2];  // (64, 1024)
    const float* Wh    = (const float*)d_in[3];  // (1024, 1024)
    const float* Ws    = (const float*)d_in[4];  // (1024, 1024)
    const float* v     = (const float*)d_in[5];  // (1024, 1)
    float* out = (float*)d_out;                  // (64, 1024)

    cudaFuncSetAttribute(logits_mma, cudaFuncAttributeMaxDynamicSharedMemorySize, SMTOT);

    tq_kernel<<<dim3(16, 4), 256>>>(query, Ws);
    transpose_wh<<<dim3(32, 32), dim3(32, 8)>>>(Wh);
    logits_mma<<<(B_ * N_) / 128, 256, SMTOT>>>(M, v);
    softmax_kernel<<<B_, N_>>>(mask);
    context_kernel<<<dim3(D_ / 256, B_), 256>>>(M, out);
}

// round 4
// speedup vs baseline: 3.8941x; 1.0896x over previous
#include <cuda_runtime.h>
#include <cuda_fp16.h>
#include <cstdint>
#include <math.h>

#define B_   64
#define N_   512
#define D_   1024

// Scratch (device globals: no allocation allowed)
__device__ float g_tq[B_ * D_];
__device__ float g_logits[B_ * N_];
__device__ float g_weights[B_ * N_];
__device__ __align__(16) __half g_Mh[B_ * N_ * D_];   // fp16 copy of M (64 MB)
__device__ __align__(16) __half g_WhTh[D_ * D_];      // Wh^T, fp16 (2 MB)

// ---------------------------------------------------------------------------
// helpers
// ---------------------------------------------------------------------------
__device__ __forceinline__ uint32_t smem_u32(const void* p) {
    uint32_t a;
    asm("{ .reg .u64 t; cvta.to.shared.u64 t, %1; cvt.u32.u64 %0, t; }" : "=r"(a) : "l"(p));
    return a;
}
__device__ __forceinline__ float tanh_fast(float x) {
    float t;
    asm("tanh.approx.f32 %0, %1;" : "=f"(t) : "f"(x));
    return t;
}
__device__ __forceinline__ void cp16(uint32_t dst, const void* src) {
    asm volatile("cp.async.cg.shared.global [%0], [%1], 16;" :: "r"(dst), "l"(src));
}
#define CP_COMMIT() asm volatile("cp.async.commit_group;" ::: "memory")
#define CP_WAIT1()  asm volatile("cp.async.wait_group 1;" ::: "memory")
#define CP_WAIT0()  asm volatile("cp.async.wait_group 0;" ::: "memory")

__device__ __forceinline__ void ldsm4(uint32_t& r0, uint32_t& r1, uint32_t& r2, uint32_t& r3,
                                      uint32_t addr) {
    asm volatile("ldmatrix.sync.aligned.m8n8.x4.shared.b16 {%0,%1,%2,%3}, [%4];"
                 : "=r"(r0), "=r"(r1), "=r"(r2), "=r"(r3) : "r"(addr));
}
__device__ __forceinline__ void mma_f16(float* d, const uint32_t* a, const uint32_t* b) {
    asm volatile("mma.sync.aligned.m16n8k16.row.col.f32.f16.f16.f32 "
                 "{%0,%1,%2,%3}, {%4,%5,%6,%7}, {%8,%9}, {%0,%1,%2,%3};"
                 : "+f"(d[0]), "+f"(d[1]), "+f"(d[2]), "+f"(d[3])
                 : "r"(a[0]), "r"(a[1]), "r"(a[2]), "r"(a[3]), "r"(b[0]), "r"(b[1]));
}

// ---------------------------------------------------------------------------
// Kernel 0: M -> fp16 (rn).  8 elements per thread, fully coalesced.
// ---------------------------------------------------------------------------
__global__ __launch_bounds__(256, 8)
void convert_m(const float* __restrict__ M)
{
    const size_t i = (size_t)blockIdx.x * 256 + threadIdx.x;   // 4,194,304 threads
    const float4* src = (const float4*)M + i * 2;
    float4 x = src[0];
    float4 y = src[1];
    __half2 h0 = __floats2half2_rn(x.x, x.y);
    __half2 h1 = __floats2half2_rn(x.z, x.w);
    __half2 h2 = __floats2half2_rn(y.x, y.y);
    __half2 h3 = __floats2half2_rn(y.z, y.w);
    uint4 o;
    o.x = *(uint32_t*)&h0; o.y = *(uint32_t*)&h1;
    o.z = *(uint32_t*)&h2; o.w = *(uint32_t*)&h3;
    ((uint4*)g_Mh)[i] = o;
}

// ---------------------------------------------------------------------------
// Kernel 1: tq = query @ Ws   (small fp32 SIMT, stays fp32 for accuracy)
// ---------------------------------------------------------------------------
__global__ void tq_kernel(const float* __restrict__ query,
                          const float* __restrict__ Ws)
{
    __shared__ float Qs[16][32];
    __shared__ float Wss[32][64];
    const int tid     = threadIdx.x;
    const int a_local = tid & 63;
    const int br      = tid >> 6;
    const int a0      = blockIdx.x * 64;
    const int b0      = blockIdx.y * 16;

    float acc[4] = {0.f, 0.f, 0.f, 0.f};
    for (int k0 = 0; k0 < D_; k0 += 32) {
        #pragma unroll
        for (int i = 0; i < 2; i++) {
            int idx = tid + i * 256;
            Qs[idx >> 5][idx & 31] = query[(b0 + (idx >> 5)) * D_ + k0 + (idx & 31)];
        }
        #pragma unroll
        for (int i = 0; i < 8; i++) {
            int idx = tid + i * 256;
            Wss[idx >> 6][idx & 63] = Ws[(k0 + (idx >> 6)) * D_ + a0 + (idx & 63)];
        }
        __syncthreads();
        #pragma unroll
        for (int kk = 0; kk < 32; kk++) {
            float wv = Wss[kk][a_local];
            #pragma unroll
            for (int q = 0; q < 4; q++) acc[q] += Qs[br + q * 4][kk] * wv;
        }
        __syncthreads();
    }
    #pragma unroll
    for (int q = 0; q < 4; q++)
        g_tq[(b0 + br + q * 4) * D_ + a0 + a_local] = acc[q];
}

// ---------------------------------------------------------------------------
// Kernel 2: WhT[c][k] = fp16_rn(Wh[k][c])
// ---------------------------------------------------------------------------
__global__ void transpose_wh(const float* __restrict__ Wh)
{
    __shared__ float t[32][33];
    const int k0 = blockIdx.y * 32, c0 = blockIdx.x * 32;
    const int tx = threadIdx.x, ty = threadIdx.y;
    for (int i = ty; i < 32; i += 8)
        t[i][tx] = Wh[(size_t)(k0 + i) * D_ + c0 + tx];
    __syncthreads();
    for (int i = ty; i < 32; i += 8)
        g_WhTh[(size_t)(c0 + i) * D_ + k0 + tx] = __float2half_rn(t[tx][i]);
}

// ---------------------------------------------------------------------------
// Kernel 3 (dominant): fp16 m16n8k16 mma GEMM + fused tanh·v epilogue
//   logits[r] = sum_c tanh( (M@Wh)[r,c] + tq[b,c] ) * v[c]
// CTA: 128 rows x 8 column tiles of 128. 8 warps (2m x 4n), warp tile 64x32.
// BK=64 fp16 (128B rows + 16B pad), cp.async double buffering.
// ---------------------------------------------------------------------------
#define ROWB  144                 // 64 halves (128B) + 16B pad: conflict-free
#define SA0   0
#define SB0   18432
#define SA1   36864
#define SB1   55296
#define SRED  73728
#define SMTOT (SRED + 512)
#define NKT   16                  // K chunks of 64 covering D=1024

__device__ __forceinline__ void stage_tile(uint32_t sdst, const char* __restrict__ src)
{
    const int tid = threadIdx.x;
    #pragma unroll
    for (int i = 0; i < 4; i++) {
        int idx = tid + i * 256;
        int r = idx >> 3, c = idx & 7;
        cp16(sdst + r * ROWB + c * 16, src + (size_t)r * 2048 + c * 16);
    }
}

__global__ __launch_bounds__(256, 2)
void logits_mma(const float* __restrict__ v)
{
    extern __shared__ char smem[];
    const uint32_t sb = smem_u32(smem);
    float* red = (float*)(smem + SRED);

    const int tid  = threadIdx.x;
    const int lane = tid & 31;
    const int wid  = tid >> 5;
    const int wm   = wid & 1;          // m block (2 x 64 rows)
    const int wn   = wid >> 1;         // n block (4 x 32 cols)
    const int g    = lane >> 2;
    const int tg   = lane & 3;

    const int row0 = blockIdx.x * 128;
    const int b    = row0 >> 9;

    if (tid < 128) red[tid] = 0.f;

    float part[8];
    #pragma unroll
    for (int i = 0; i < 8; i++) part[i] = 0.f;

    // ldmatrix smem offsets (within a buffer)
    // A x4: m0 rows0-7 k0-7, m1 rows8-15 k0-7, m2 rows0-7 k8-15, m3 rows8-15 k8-15
    const uint32_t a_off = (uint32_t)((wm * 64 + (lane & 15)) * ROWB + (lane >> 4) * 16);
    // B x4: m0 n0-7 k0-7, m1 n0-7 k8-15, m2 n8-15 k0-7, m3 n8-15 k8-15
    const uint32_t b_off = (uint32_t)((wn * 32 + (lane & 7) + ((lane >> 4) & 1) * 8) * ROWB
                                      + ((lane >> 3) & 1) * 16);

    for (int c0 = 0; c0 < D_; c0 += 128) {
        const char* Abase = (const char*)(g_Mh + (size_t)row0 * D_);
        const char* Bbase = (const char*)(g_WhTh + (size_t)c0 * D_);

        float acc[4][4][4];
        #pragma unroll
        for (int mi = 0; mi < 4; mi++)
            #pragma unroll
            for (int ni = 0; ni < 4; ni++)
                #pragma unroll
                for (int q = 0; q < 4; q++) acc[mi][ni][q] = 0.f;

        // prologue: stage chunks 0,1 (each chunk = 64 K-halves = 128 B/row)
        stage_tile(sb + SA0, Abase + 0);
        stage_tile(sb + SB0, Bbase + 0);
        CP_COMMIT();
        stage_tile(sb + SA1, Abase + 128);
        stage_tile(sb + SB1, Bbase + 128);
        CP_COMMIT();

        for (int kt = 0; kt < NKT; kt++) {
            if (kt == NKT - 1) CP_WAIT0(); else CP_WAIT1();
            __syncthreads();

            const uint32_t sA = sb + ((kt & 1) ? SA1 : SA0);
            const uint32_t sB = sb + ((kt & 1) ? SB1 : SB0);

            #pragma unroll
            for (int ks = 0; ks < 4; ks++) {     // 4 x k16 within the 64-chunk
                uint32_t a[4][4];
                #pragma unroll
                for (int mi = 0; mi < 4; mi++)
                    ldsm4(a[mi][0], a[mi][1], a[mi][2], a[mi][3],
                          sA + a_off + mi * (16 * ROWB) + ks * 32);
                uint32_t bf[4][2];
                #pragma unroll
                for (int np = 0; np < 2; np++) {
                    uint32_t r0, r1, r2, r3;
                    ldsm4(r0, r1, r2, r3, sB + b_off + np * (16 * ROWB) + ks * 32);
                    bf[np * 2 + 0][0] = r0; bf[np * 2 + 0][1] = r1;
                    bf[np * 2 + 1][0] = r2; bf[np * 2 + 1][1] = r3;
                }
                #pragma unroll
                for (int mi = 0; mi < 4; mi++)
                    #pragma unroll
                    for (int ni = 0; ni < 4; ni++)
                        mma_f16(acc[mi][ni], a[mi], bf[ni]);
            }
            __syncthreads();
            if (kt + 2 < NKT) {
                const uint32_t dA = sb + ((kt & 1) ? SA1 : SA0);
                const uint32_t dB = sb + ((kt & 1) ? SB1 : SB0);
                stage_tile(dA, Abase + (size_t)(kt + 2) * 128);
                stage_tile(dB, Bbase + (size_t)(kt + 2) * 128);
                CP_COMMIT();
            } else {
                CP_COMMIT();   // keep group counting uniform
            }
        }

        // fused epilogue for this column tile
        #pragma unroll
        for (int ni = 0; ni < 4; ni++) {
            const int cg = c0 + wn * 32 + ni * 8 + tg * 2;
            const float tq0 = __ldg(&g_tq[b * D_ + cg]);
            const float tq1 = __ldg(&g_tq[b * D_ + cg + 1]);
            const float v0  = __ldg(&v[cg]);
            const float v1  = __ldg(&v[cg + 1]);
            #pragma unroll
            for (int mi = 0; mi < 4; mi++) {
                part[2 * mi]     += tanh_fast(acc[mi][ni][0] + tq0) * v0
                                  + tanh_fast(acc[mi][ni][1] + tq1) * v1;
                part[2 * mi + 1] += tanh_fast(acc[mi][ni][2] + tq0) * v0
                                  + tanh_fast(acc[mi][ni][3] + tq1) * v1;
            }
        }
        __syncthreads();   // before restaging buffers next c0 iter
    }

    // reduce partials: lanes tg=0..3 hold disjoint cols of same rows
    #pragma unroll
    for (int i = 0; i < 8; i++) {
        float p = part[i];
        p += __shfl_xor_sync(0xFFFFFFFFu, p, 1);
        p += __shfl_xor_sync(0xFFFFFFFFu, p, 2);
        if (tg == 0) {
            int row = wm * 64 + (i >> 1) * 16 + (i & 1) * 8 + g;
            atomicAdd(&red[row], p);
        }
    }
    __syncthreads();
    if (tid < 128) g_logits[row0 + tid] = red[tid];
}

// ---------------------------------------------------------------------------
// Kernel 4: masked softmax per batch row
// ---------------------------------------------------------------------------
__global__ void softmax_kernel(const int* __restrict__ mask)
{
    __shared__ float sm[N_];
    const int b = blockIdx.x;
    const int t = threadIdx.x;

    const int   mk = mask[b * N_ + t];
    const float l  = g_logits[b * N_ + t];

    int any = __syncthreads_or(mk != 0);
    if (!any) {
        g_weights[b * N_ + t] = 0.f;
        return;
    }
    float x = (mk != 0) ? l : -1e30f;

    sm[t] = x;
    __syncthreads();
    #pragma unroll
    for (int s = 256; s > 0; s >>= 1) {
        if (t < s) sm[t] = fmaxf(sm[t], sm[t + s]);
        __syncthreads();
    }
    float mx = sm[0];
    __syncthreads();

    float e = expf(x - mx);
    sm[t] = e;
    __syncthreads();
    #pragma unroll
    for (int s = 256; s > 0; s >>= 1) {
        if (t < s) sm[t] += sm[t + s];
        __syncthreads();
    }
    g_weights[b * N_ + t] = e / sm[0];
}

// ---------------------------------------------------------------------------
// Kernel 5: context[b,:] = weights[b,:] @ M[b,:,:]  (DRAM-bound, fp32 M)
// 8 independent accumulators -> MLP 8
// ---------------------------------------------------------------------------
__global__ __launch_bounds__(256, 4)
void context_kernel(const float* __restrict__ M, float* __restrict__ out)
{
    __shared__ float ws[N_];
    const int b = blockIdx.y;
    const int d = blockIdx.x * 256 + threadIdx.x;
    for (int i = threadIdx.x; i < N_; i += 256)
        ws[i] = g_weights[b * N_ + i];
    __syncthreads();

    const float* Mb = M + (size_t)b * N_ * D_ + d;
    float a0 = 0.f, a1 = 0.f, a2 = 0.f, a3 = 0.f;
    float a4 = 0.f, a5 = 0.f, a6 = 0.f, a7 = 0.f;
    #pragma unroll 2
    for (int n = 0; n < N_; n += 8) {
        a0 += ws[n + 0] * Mb[(size_t)(n + 0) * D_];
        a1 += ws[n + 1] * Mb[(size_t)(n + 1) * D_];
        a2 += ws[n + 2] * Mb[(size_t)(n + 2) * D_];
        a3 += ws[n + 3] * Mb[(size_t)(n + 3) * D_];
        a4 += ws[n + 4] * Mb[(size_t)(n + 4) * D_];
        a5 += ws[n + 5] * Mb[(size_t)(n + 5) * D_];
        a6 += ws[n + 6] * Mb[(size_t)(n + 6) * D_];
        a7 += ws[n + 7] * Mb[(size_t)(n + 7) * D_];
    }
    out[b * D_ + d] = ((a0 + a1) + (a2 + a3)) + ((a4 + a5) + (a6 + a7));
}

// ---------------------------------------------------------------------------
extern "C" void kernel_launch(void* const* d_in, const int* in_sizes, int n_in,
                              void* d_out, int out_size)
{
    const float* M     = (const float*)d_in[0];  // (64, 512, 1024)
    const int*   mask  = (const int*)  d_in[1];  // (64, 512)
    const float* query = (const float*)d_in[2];  // (64, 1024)
    const float* Wh    = (const float*)d_in[3];  // (1024, 1024)
    const float* Ws    = (const float*)d_in[4];  // (1024, 1024)
    const float* v     = (const float*)d_in[5];  // (1024, 1)
    float* out = (float*)d_out;                  // (64, 1024)

    cudaFuncSetAttribute(logits_mma, cudaFuncAttributeMaxDynamicSharedMemorySize, SMTOT);

    convert_m<<<(B_ * N_ * D_) / (256 * 8), 256>>>(M);
    tq_kernel<<<dim3(16, 4), 256>>>(query, Ws);
    transpose_wh<<<dim3(32, 32), dim3(32, 8)>>>(Wh);
    logits_mma<<<(B_ * N_) / 128, 256, SMTOT>>>(v);
    softmax_kernel<<<B_, N_>>>(mask);
    context_kernel<<<dim3(D_ / 256, B_), 256>>>(M, out);
}

// round 8
// speedup vs baseline: 5.9032x; 1.5159x over previous
#include <cuda_runtime.h>
#include <cuda_fp16.h>
#include <cstdint>
#include <math.h>

#define B_   64
#define N_   512
#define D_   1024

// Scratch (device globals: no allocation allowed)
__device__ float g_tq[B_ * D_];
__device__ float g_logits[B_ * N_];
__device__ float g_weights[B_ * N_];
__device__ __align__(16) __half g_Mh[B_ * N_ * D_];   // fp16 copy of M (64 MB)
__device__ __align__(16) __half g_WhTh[D_ * D_];      // Wh^T, fp16 (2 MB)

// ---------------------------------------------------------------------------
// helpers
// ---------------------------------------------------------------------------
__device__ __forceinline__ uint32_t smem_u32(const void* p) {
    uint32_t a;
    asm("{ .reg .u64 t; cvta.to.shared.u64 t, %1; cvt.u32.u64 %0, t; }" : "=r"(a) : "l"(p));
    return a;
}
__device__ __forceinline__ float tanh_fast(float x) {
    float t;
    asm("tanh.approx.f32 %0, %1;" : "=f"(t) : "f"(x));
    return t;
}
__device__ __forceinline__ void cp16(uint32_t dst, const void* src) {
    asm volatile("cp.async.cg.shared.global [%0], [%1], 16;" :: "r"(dst), "l"(src));
}
#define CP_COMMIT() asm volatile("cp.async.commit_group;" ::: "memory")
#define CP_WAIT1()  asm volatile("cp.async.wait_group 1;" ::: "memory")

__device__ __forceinline__ void ldsm4(uint32_t& r0, uint32_t& r1, uint32_t& r2, uint32_t& r3,
                                      uint32_t addr) {
    asm volatile("ldmatrix.sync.aligned.m8n8.x4.shared.b16 {%0,%1,%2,%3}, [%4];"
                 : "=r"(r0), "=r"(r1), "=r"(r2), "=r"(r3) : "r"(addr));
}
__device__ __forceinline__ void mma_f16(float* d, const uint32_t* a, const uint32_t* b) {
    asm volatile("mma.sync.aligned.m16n8k16.row.col.f32.f16.f16.f32 "
                 "{%0,%1,%2,%3}, {%4,%5,%6,%7}, {%8,%9}, {%0,%1,%2,%3};"
                 : "+f"(d[0]), "+f"(d[1]), "+f"(d[2]), "+f"(d[3])
                 : "r"(a[0]), "r"(a[1]), "r"(a[2]), "r"(a[3]), "r"(b[0]), "r"(b[1]));
}

// ---------------------------------------------------------------------------
// Kernel 0: M -> fp16 (rn). 8 elements per thread, fully coalesced.
// ---------------------------------------------------------------------------
__global__ __launch_bounds__(256, 8)
void convert_m(const float* __restrict__ M)
{
    const size_t i = (size_t)blockIdx.x * 256 + threadIdx.x;
    const float4* src = (const float4*)M + i * 2;
    float4 x = src[0];
    float4 y = src[1];
    __half2 h0 = __floats2half2_rn(x.x, x.y);
    __half2 h1 = __floats2half2_rn(x.z, x.w);
    __half2 h2 = __floats2half2_rn(y.x, y.y);
    __half2 h3 = __floats2half2_rn(y.z, y.w);
    uint4 o;
    o.x = *(uint32_t*)&h0; o.y = *(uint32_t*)&h1;
    o.z = *(uint32_t*)&h2; o.w = *(uint32_t*)&h3;
    ((uint4*)g_Mh)[i] = o;
}

// ---------------------------------------------------------------------------
// Kernel 1: tq = query @ Ws   (small fp32 SIMT, stays fp32 for accuracy)
// ---------------------------------------------------------------------------
__global__ void tq_kernel(const float* __restrict__ query,
                          const float* __restrict__ Ws)
{
    __shared__ float Qs[16][32];
    __shared__ float Wss[32][64];
    const int tid     = threadIdx.x;
    const int a_local = tid & 63;
    const int br      = tid >> 6;
    const int a0      = blockIdx.x * 64;
    const int b0      = blockIdx.y * 16;

    float acc[4] = {0.f, 0.f, 0.f, 0.f};
    for (int k0 = 0; k0 < D_; k0 += 32) {
        #pragma unroll
        for (int i = 0; i < 2; i++) {
            int idx = tid + i * 256;
            Qs[idx >> 5][idx & 31] = query[(b0 + (idx >> 5)) * D_ + k0 + (idx & 31)];
        }
        #pragma unroll
        for (int i = 0; i < 8; i++) {
            int idx = tid + i * 256;
            Wss[idx >> 6][idx & 63] = Ws[(k0 + (idx >> 6)) * D_ + a0 + (idx & 63)];
        }
        __syncthreads();
        #pragma unroll
        for (int kk = 0; kk < 32; kk++) {
            float wv = Wss[kk][a_local];
            #pragma unroll
            for (int q = 0; q < 4; q++) acc[q] += Qs[br + q * 4][kk] * wv;
        }
        __syncthreads();
    }
    #pragma unroll
    for (int q = 0; q < 4; q++)
        g_tq[(b0 + br + q * 4) * D_ + a0 + a_local] = acc[q];
}

// ---------------------------------------------------------------------------
// Kernel 2: WhT[c][k] = fp16_rn(Wh[k][c])
// ---------------------------------------------------------------------------
__global__ void transpose_wh(const float* __restrict__ Wh)
{
    __shared__ float t[32][33];
    const int k0 = blockIdx.y * 32, c0 = blockIdx.x * 32;
    const int tx = threadIdx.x, ty = threadIdx.y;
    for (int i = ty; i < 32; i += 8)
        t[i][tx] = Wh[(size_t)(k0 + i) * D_ + c0 + tx];
    __syncthreads();
    for (int i = ty; i < 32; i += 8)
        g_WhTh[(size_t)(c0 + i) * D_ + k0 + tx] = __float2half_rn(t[tx][i]);
}

// ---------------------------------------------------------------------------
// Kernel 3 (dominant): fp16 m16n8k16 mma GEMM + fused tanh·v epilogue
//   logits[r] = sum_c tanh( (M@Wh)[r,c] + tq[b,c] ) * v[c]
// CTA: 128 rows x 8 column tiles of 128. 8 warps (2m x 4n), warp tile 64x32.
// BK=64 fp16, 3-stage cp.async pipeline, ONE __syncthreads per K-chunk.
// ---------------------------------------------------------------------------
#define ROWB  144                 // 64 halves (128B) + 16B pad
#define STG   36864               // one stage: A (18432) + B (18432)
#define SA(s) ((s) * STG)
#define SB(s) ((s) * STG + 18432)
#define SRED  (3 * STG)           // 110592
#define SMTOT (SRED + 512)
#define NKT   16                  // K chunks of 64 covering D=1024

__device__ __forceinline__ void stage_tile(uint32_t sdst, const char* __restrict__ src)
{
    const int tid = threadIdx.x;
    #pragma unroll
    for (int i = 0; i < 4; i++) {
        int idx = tid + i * 256;
        int r = idx >> 3, c = idx & 7;
        cp16(sdst + r * ROWB + c * 16, src + (size_t)r * 2048 + c * 16);
    }
}

__global__ __launch_bounds__(256, 2)
void logits_mma(const float* __restrict__ v)
{
    extern __shared__ char smem[];
    const uint32_t sb = smem_u32(smem);
    float* red = (float*)(smem + SRED);

    const int tid  = threadIdx.x;
    const int lane = tid & 31;
    const int wid  = tid >> 5;
    const int wm   = wid & 1;          // m block (2 x 64 rows)
    const int wn   = wid >> 1;         // n block (4 x 32 cols)
    const int g    = lane >> 2;
    const int tg   = lane & 3;

    const int row0 = blockIdx.x * 128;
    const int b    = row0 >> 9;

    if (tid < 128) red[tid] = 0.f;

    float part[8];
    #pragma unroll
    for (int i = 0; i < 8; i++) part[i] = 0.f;

    // ldmatrix smem offsets (within a stage)
    const uint32_t a_off = (uint32_t)((wm * 64 + (lane & 15)) * ROWB + (lane >> 4) * 16);
    const uint32_t b_off = (uint32_t)((wn * 32 + (lane & 7) + ((lane >> 4) & 1) * 8) * ROWB
                                      + ((lane >> 3) & 1) * 16);

    const char* Abase = (const char*)(g_Mh + (size_t)row0 * D_);

    for (int c0 = 0; c0 < D_; c0 += 128) {
        const char* Bbase = (const char*)(g_WhTh + (size_t)c0 * D_);

        float acc[4][4][4];
        #pragma unroll
        for (int mi = 0; mi < 4; mi++)
            #pragma unroll
            for (int ni = 0; ni < 4; ni++)
                #pragma unroll
                for (int q = 0; q < 4; q++) acc[mi][ni][q] = 0.f;

        // prologue: stage chunks 0,1 into stages 0,1
        stage_tile(sb + SA(0), Abase + 0);
        stage_tile(sb + SB(0), Bbase + 0);
        CP_COMMIT();
        stage_tile(sb + SA(1), Abase + 128);
        stage_tile(sb + SB(1), Bbase + 128);
        CP_COMMIT();

        int buf = 0, nbuf = 2;
        for (int kt = 0; kt < NKT; kt++) {
            CP_WAIT1();            // chunk kt complete (1 newest still in flight)
            __syncthreads();       // nbuf's previous readers (iter kt-1) are done

            // issue copies for chunk kt+2 BEFORE mma so LDGSTS overlaps compute
            if (kt + 2 < NKT) {
                stage_tile(sb + SA(nbuf), Abase + (size_t)(kt + 2) * 128);
                stage_tile(sb + SB(nbuf), Bbase + (size_t)(kt + 2) * 128);
            }
            CP_COMMIT();           // uniform group counting

            const uint32_t sA = sb + SA(buf);
            const uint32_t sBp = sb + SB(buf);

            #pragma unroll
            for (int ks = 0; ks < 4; ks++) {     // 4 x k16 within the 64-chunk
                uint32_t a[4][4];
                #pragma unroll
                for (int mi = 0; mi < 4; mi++)
                    ldsm4(a[mi][0], a[mi][1], a[mi][2], a[mi][3],
                          sA + a_off + mi * (16 * ROWB) + ks * 32);
                uint32_t bf[4][2];
                #pragma unroll
                for (int np = 0; np < 2; np++) {
                    uint32_t r0, r1, r2, r3;
                    ldsm4(r0, r1, r2, r3, sBp + b_off + np * (16 * ROWB) + ks * 32);
                    bf[np * 2 + 0][0] = r0; bf[np * 2 + 0][1] = r1;
                    bf[np * 2 + 1][0] = r2; bf[np * 2 + 1][1] = r3;
                }
                #pragma unroll
                for (int mi = 0; mi < 4; mi++)
                    #pragma unroll
                    for (int ni = 0; ni < 4; ni++)
                        mma_f16(acc[mi][ni], a[mi], bf[ni]);
            }
            buf  = (buf  == 2) ? 0 : buf  + 1;
            nbuf = (nbuf == 2) ? 0 : nbuf + 1;
        }

        // fused epilogue for this column tile
        #pragma unroll
        for (int ni = 0; ni < 4; ni++) {
            const int cg = c0 + wn * 32 + ni * 8 + tg * 2;
            const float tq0 = __ldg(&g_tq[b * D_ + cg]);
            const float tq1 = __ldg(&g_tq[b * D_ + cg + 1]);
            const float v0  = __ldg(&v[cg]);
            const float v1  = __ldg(&v[cg + 1]);
            #pragma unroll
            for (int mi = 0; mi < 4; mi++) {
                part[2 * mi]     += tanh_fast(acc[mi][ni][0] + tq0) * v0
                                  + tanh_fast(acc[mi][ni][1] + tq1) * v1;
                part[2 * mi + 1] += tanh_fast(acc[mi][ni][2] + tq0) * v0
                                  + tanh_fast(acc[mi][ni][3] + tq1) * v1;
            }
        }
        __syncthreads();   // all mma/epilogue done before next c0 restages buffers
    }

    // reduce partials: lanes tg=0..3 hold disjoint cols of same rows
    #pragma unroll
    for (int i = 0; i < 8; i++) {
        float p = part[i];
        p += __shfl_xor_sync(0xFFFFFFFFu, p, 1);
        p += __shfl_xor_sync(0xFFFFFFFFu, p, 2);
        if (tg == 0) {
            int row = wm * 64 + (i >> 1) * 16 + (i & 1) * 8 + g;
            atomicAdd(&red[row], p);
        }
    }
    __syncthreads();
    if (tid < 128) g_logits[row0 + tid] = red[tid];
}

// ---------------------------------------------------------------------------
// Kernel 4: masked softmax per batch row
// ---------------------------------------------------------------------------
__global__ void softmax_kernel(const int* __restrict__ mask)
{
    __shared__ float sm[N_];
    const int b = blockIdx.x;
    const int t = threadIdx.x;

    const int   mk = mask[b * N_ + t];
    const float l  = g_logits[b * N_ + t];

    int any = __syncthreads_or(mk != 0);
    if (!any) {
        g_weights[b * N_ + t] = 0.f;
        return;
    }
    float x = (mk != 0) ? l : -1e30f;

    sm[t] = x;
    __syncthreads();
    #pragma unroll
    for (int s = 256; s > 0; s >>= 1) {
        if (t < s) sm[t] = fmaxf(sm[t], sm[t + s]);
        __syncthreads();
    }
    float mx = sm[0];
    __syncthreads();

    float e = expf(x - mx);
    sm[t] = e;
    __syncthreads();
    #pragma unroll
    for (int s = 256; s > 0; s >>= 1) {
        if (t < s) sm[t] += sm[t + s];
        __syncthreads();
    }
    g_weights[b * N_ + t] = e / sm[0];
}

// ---------------------------------------------------------------------------
// Kernel 5: context[b,:] = weights[b,:] @ Mh[b,:,:]  (fp16 M: half the DRAM)
// 128 threads, each owns 2 adjacent d-cols via __half2; warp = 128B lines.
// ---------------------------------------------------------------------------
__global__ __launch_bounds__(128, 8)
void context_kernel(float* __restrict__ out)
{
    __shared__ float ws[N_];
    const int b  = blockIdx.y;
    const int d2 = blockIdx.x * 128 + threadIdx.x;   // half2 index
    for (int i = threadIdx.x; i < N_; i += 128)
        ws[i] = g_weights[b * N_ + i];
    __syncthreads();

    const __half2* Mb = (const __half2*)(g_Mh + (size_t)b * N_ * D_) + d2;
    float2 a0 = {0.f, 0.f}, a1 = {0.f, 0.f}, a2 = {0.f, 0.f}, a3 = {0.f, 0.f};
    #pragma unroll 2
    for (int n = 0; n < N_; n += 4) {
        float2 m0 = __half22float2(Mb[(size_t)(n + 0) * (D_ / 2)]);
        float2 m1 = __half22float2(Mb[(size_t)(n + 1) * (D_ / 2)]);
        float2 m2 = __half22float2(Mb[(size_t)(n + 2) * (D_ / 2)]);
        float2 m3 = __half22float2(Mb[(size_t)(n + 3) * (D_ / 2)]);
        a0.x += ws[n + 0] * m0.x; a0.y += ws[n + 0] * m0.y;
        a1.x += ws[n + 1] * m1.x; a1.y += ws[n + 1] * m1.y;
        a2.x += ws[n + 2] * m2.x; a2.y += ws[n + 2] * m2.y;
        a3.x += ws[n + 3] * m3.x; a3.y += ws[n + 3] * m3.y;
    }
    float2 r;
    r.x = (a0.x + a1.x) + (a2.x + a3.x);
    r.y = (a0.y + a1.y) + (a2.y + a3.y);
    ((float2*)(out + b * D_))[d2] = r;
}

// ---------------------------------------------------------------------------
extern "C" void kernel_launch(void* const* d_in, const int* in_sizes, int n_in,
                              void* d_out, int out_size)
{
    const float* M     = (const float*)d_in[0];  // (64, 512, 1024)
    const int*   mask  = (const int*)  d_in[1];  // (64, 512)
    const float* query = (const float*)d_in[2];  // (64, 1024)
    const float* Wh    = (const float*)d_in[3];  // (1024, 1024)
    const float* Ws    = (const float*)d_in[4];  // (1024, 1024)
    const float* v     = (const float*)d_in[5];  // (1024, 1)
    float* out = (float*)d_out;                  // (64, 1024)

    cudaFuncSetAttribute(logits_mma, cudaFuncAttributeMaxDynamicSharedMemorySize, SMTOT);

    convert_m<<<(B_ * N_ * D_) / (256 * 8), 256>>>(M);
    tq_kernel<<<dim3(16, 4), 256>>>(query, Ws);
    transpose_wh<<<dim3(32, 32), dim3(32, 8)>>>(Wh);
    logits_mma<<<(B_ * N_) / 128, 256, SMTOT>>>(v);
    softmax_kernel<<<B_, N_>>>(mask);
    context_kernel<<<dim3(D_ / 256, B_), 128>>>(out);
}

// round 9
// speedup vs baseline: 7.2047x; 1.2205x over previous
#include <cuda_runtime.h>
#include <cuda_fp16.h>
#include <cstdint>
#include <math.h>

#define B_   64
#define N_   512
#define D_   1024

#define CHB  18432            // one chunk: 128 rows x 144 B (64 halves + 16B pad)
#define RB_  256              // A row-blocks (128 rows each)
#define KT_  16               // K chunks of 64
#define CT_  8                // B column tiles of 128

// Scratch (device globals: no allocation allowed)
__device__ float g_tq[B_ * D_];
__device__ float g_logits[B_ * N_];
__device__ __align__(128) unsigned char g_MhT[RB_ * KT_ * CHB];  // tiled fp16 A (72 MB)
__device__ __align__(128) unsigned char g_WhT[CT_ * KT_ * CHB];  // tiled fp16 Wh^T (2.25 MB)

// ---------------------------------------------------------------------------
// helpers
// ---------------------------------------------------------------------------
__device__ __forceinline__ uint32_t smem_u32(const void* p) {
    uint32_t a;
    asm("{ .reg .u64 t; cvta.to.shared.u64 t, %1; cvt.u32.u64 %0, t; }" : "=r"(a) : "l"(p));
    return a;
}
__device__ __forceinline__ float tanh_fast(float x) {
    float t;
    asm("tanh.approx.f32 %0, %1;" : "=f"(t) : "f"(x));
    return t;
}
__device__ __forceinline__ void ldsm4(uint32_t& r0, uint32_t& r1, uint32_t& r2, uint32_t& r3,
                                      uint32_t addr) {
    asm volatile("ldmatrix.sync.aligned.m8n8.x4.shared.b16 {%0,%1,%2,%3}, [%4];"
                 : "=r"(r0), "=r"(r1), "=r"(r2), "=r"(r3) : "r"(addr));
}
__device__ __forceinline__ void mma_f16(float* d, const uint32_t* a, const uint32_t* b) {
    asm volatile("mma.sync.aligned.m16n8k16.row.col.f32.f16.f16.f32 "
                 "{%0,%1,%2,%3}, {%4,%5,%6,%7}, {%8,%9}, {%0,%1,%2,%3};"
                 : "+f"(d[0]), "+f"(d[1]), "+f"(d[2]), "+f"(d[3])
                 : "r"(a[0]), "r"(a[1]), "r"(a[2]), "r"(a[3]), "r"(b[0]), "r"(b[1]));
}
__device__ __forceinline__ void mbar_init(uint32_t mb, uint32_t cnt) {
    asm volatile("mbarrier.init.shared.b64 [%0], %1;" :: "r"(mb), "r"(cnt) : "memory");
}
__device__ __forceinline__ void mbar_wait(uint32_t mb, uint32_t parity) {
    uint32_t done;
    asm volatile(
        "{\n\t.reg .pred p;\n\t"
        "mbarrier.try_wait.parity.acquire.cta.shared::cta.b64 p, [%1], %2;\n\t"
        "selp.b32 %0, 1, 0, p;\n\t}"
        : "=r"(done) : "r"(mb), "r"(parity) : "memory");
    if (!done) {
        asm volatile(
            "{\n\t.reg .pred P1;\n\t"
            "WL_%=:\n\t"
            "mbarrier.try_wait.parity.acquire.cta.shared::cta.b64 P1, [%0], %1, 0x989680;\n\t"
            "@P1 bra.uni WD_%=;\n\t"
            "bra.uni WL_%=;\n\t"
            "WD_%=:\n\t}"
            :: "r"(mb), "r"(parity) : "memory");
    }
}
// issue one chunk: A (18432 B) + B (18432 B) into stage, tracked by one mbarrier
__device__ __forceinline__ void tma_chunk(uint32_t sdst, const void* asrc,
                                          const void* bsrc, uint32_t mbar) {
    asm volatile("mbarrier.arrive.expect_tx.shared.b64 _, [%0], %1;"
                 :: "r"(mbar), "r"(2u * CHB) : "memory");
    asm volatile("cp.async.bulk.shared::cluster.global.mbarrier::complete_tx::bytes "
                 "[%0], [%1], %2, [%3];"
                 :: "r"(sdst), "l"(asrc), "r"((uint32_t)CHB), "r"(mbar) : "memory");
    asm volatile("cp.async.bulk.shared::cluster.global.mbarrier::complete_tx::bytes "
                 "[%0], [%1], %2, [%3];"
                 :: "r"(sdst + CHB), "l"(bsrc), "r"((uint32_t)CHB), "r"(mbar) : "memory");
}

// ---------------------------------------------------------------------------
// Kernel 1 (fused prep): tq = query@Ws (blocks 0..63, first so it overlaps),
// WhT tiled fp16 (next 1024 blocks), M -> tiled fp16 (remaining 16384 blocks)
// ---------------------------------------------------------------------------
#define TQ_BLKS   64
#define TRAN_BLKS 1024
#define CONV_BLKS 16384

__global__ __launch_bounds__(256)
void prep_kernel(const float* __restrict__ M, const float* __restrict__ Wh,
                 const float* __restrict__ query, const float* __restrict__ Ws)
{
    __shared__ float sbuf[2624];
    const int bid = blockIdx.x;
    const int tid = threadIdx.x;

    if (bid < TQ_BLKS) {
        // ----- tq = query @ Ws -----
        float (*Qs)[32]  = (float(*)[32])sbuf;          // 16 x 32
        float (*Wss)[64] = (float(*)[64])(sbuf + 512);  // 32 x 64
        const int a_local = tid & 63;
        const int br      = tid >> 6;
        const int a0      = (bid & 15) * 64;
        const int b0      = (bid >> 4) * 16;

        float acc[4] = {0.f, 0.f, 0.f, 0.f};
        for (int k0 = 0; k0 < D_; k0 += 32) {
            #pragma unroll
            for (int i = 0; i < 2; i++) {
                int idx = tid + i * 256;
                Qs[idx >> 5][idx & 31] = query[(b0 + (idx >> 5)) * D_ + k0 + (idx & 31)];
            }
            #pragma unroll
            for (int i = 0; i < 8; i++) {
                int idx = tid + i * 256;
                Wss[idx >> 6][idx & 63] = Ws[(size_t)(k0 + (idx >> 6)) * D_ + a0 + (idx & 63)];
            }
            __syncthreads();
            #pragma unroll
            for (int kk = 0; kk < 32; kk++) {
                float wv = Wss[kk][a_local];
                #pragma unroll
                for (int q = 0; q < 4; q++) acc[q] += Qs[br + q * 4][kk] * wv;
            }
            __syncthreads();
        }
        #pragma unroll
        for (int q = 0; q < 4; q++)
            g_tq[(b0 + br + q * 4) * D_ + a0 + a_local] = acc[q];
    } else if (bid < TQ_BLKS + TRAN_BLKS) {
        // ----- WhT tiled: chunk (ct,kt), row = out-col c, 64 halves of k -----
        const int t  = bid - TQ_BLKS;
        const int kb = t >> 5, cb = t & 31;
        const int k0 = kb * 32, c0 = cb * 32;
        float (*tr)[33] = (float(*)[33])sbuf;
        #pragma unroll
        for (int j = 0; j < 4; j++) {
            int idx = tid + j * 256;
            int i = idx >> 5, x = idx & 31;
            tr[i][x] = Wh[(size_t)(k0 + i) * D_ + c0 + x];
        }
        __syncthreads();
        const int ct = c0 >> 7;
        const int kt = kb >> 1;
        const int hb = (kb & 1) * 32;
        unsigned char* dst = g_WhT + (size_t)(ct * 16 + kt) * CHB;
        #pragma unroll
        for (int j = 0; j < 4; j++) {
            int idx = tid + j * 256;
            int i = idx >> 5, x = idx & 31;
            int rloc = (c0 & 127) + i;
            *(__half*)(dst + rloc * 144 + (hb + x) * 2) = __float2half_rn(tr[x][i]);
        }
    } else {
        // ----- M -> tiled fp16: one 16B unit (8 halves) per thread -----
        const uint32_t u  = (uint32_t)(bid - TQ_BLKS - TRAN_BLKS) * 256 + tid;
        const uint32_t c  = u & 7;
        const uint32_t r  = (u >> 3) & 127;
        const uint32_t kt = (u >> 10) & 15;
        const uint32_t rb = u >> 14;
        const float4* src = (const float4*)(M + ((size_t)(rb * 128 + r) << 10) + kt * 64 + c * 8);
        float4 x = src[0];
        float4 y = src[1];
        __half2 h0 = __floats2half2_rn(x.x, x.y);
        __half2 h1 = __floats2half2_rn(x.z, x.w);
        __half2 h2 = __floats2half2_rn(y.x, y.y);
        __half2 h3 = __floats2half2_rn(y.z, y.w);
        uint4 o;
        o.x = *(uint32_t*)&h0; o.y = *(uint32_t*)&h1;
        o.z = *(uint32_t*)&h2; o.w = *(uint32_t*)&h3;
        *(uint4*)(g_MhT + (size_t)(rb * 16 + kt) * CHB + r * 144 + c * 16) = o;
    }
}

// ---------------------------------------------------------------------------
// Kernel 2 (dominant): fp16 m16n8k16 mma GEMM + fused tanh·v epilogue
// Bulk-async staged (one thread issues 2x18KB per chunk), 3-stage mbarrier
// ring, flattened 128-chunk loop (8 c-tiles x 16 K-chunks).
// ---------------------------------------------------------------------------
#define ROWB  144
#define STG   (2 * CHB)           // 36864: A + B for one chunk
#define SRED  (3 * STG)           // 110592
#define SMB   (SRED + 512)        // 3 mbarriers
#define SMTOT (SMB + 24)

__global__ __launch_bounds__(256, 2)
void logits_mma(const float* __restrict__ v)
{
    extern __shared__ char smem[];
    const uint32_t sb = smem_u32(smem);
    float* red = (float*)(smem + SRED);

    const int tid  = threadIdx.x;
    const int lane = tid & 31;
    const int wid  = tid >> 5;
    const int wm   = wid & 1;          // m block (2 x 64 rows)
    const int wn   = wid >> 1;         // n block (4 x 32 cols)
    const int gq   = lane >> 2;
    const int tg   = lane & 3;

    const int rb   = blockIdx.x;
    const int row0 = rb * 128;
    const int b    = row0 >> 9;

    if (tid < 128) red[tid] = 0.f;
    if (tid == 0) {
        mbar_init(sb + SMB + 0, 1);
        mbar_init(sb + SMB + 8, 1);
        mbar_init(sb + SMB + 16, 1);
        asm volatile("fence.proxy.async.shared::cta;" ::: "memory");
    }
    __syncthreads();

    float part[8];
    #pragma unroll
    for (int i = 0; i < 8; i++) part[i] = 0.f;

    // ldsm smem offsets within a stage (A at +0, B at +CHB)
    const uint32_t a_off = (uint32_t)((wm * 64 + (lane & 15)) * ROWB + (lane >> 4) * 16);
    const uint32_t b_off = (uint32_t)((wn * 32 + (lane & 7) + ((lane >> 4) & 1) * 8) * ROWB
                                      + ((lane >> 3) & 1) * 16 + CHB);

    const unsigned char* Abase = g_MhT + (size_t)rb * (KT_ * CHB);

    // prologue: issue chunks 0 and 1
    if (tid == 0) {
        tma_chunk(sb + 0,   Abase + 0 * CHB, g_WhT + 0 * CHB, sb + SMB + 0);
        tma_chunk(sb + STG, Abase + 1 * CHB, g_WhT + 1 * CHB, sb + SMB + 8);
    }

    uint32_t phases = 0;
    int s = 0;
    float acc[4][4][4];

    for (int ch = 0; ch < 128; ch++) {
        const int kt = ch & 15;
        if (kt == 0) {
            #pragma unroll
            for (int mi = 0; mi < 4; mi++)
                #pragma unroll
                for (int ni = 0; ni < 4; ni++)
                    #pragma unroll
                    for (int q = 0; q < 4; q++) acc[mi][ni][q] = 0.f;
        }

        mbar_wait(sb + SMB + s * 8, (phases >> s) & 1);   // chunk ch staged
        phases ^= (1u << s);
        __syncthreads();                                   // stage s2 free of readers

        if (tid == 0 && ch + 2 < 128) {
            const int ch2 = ch + 2;
            int s2 = s + 2; if (s2 >= 3) s2 -= 3;
            tma_chunk(sb + s2 * STG,
                      Abase + (size_t)(ch2 & 15) * CHB,
                      g_WhT + (size_t)(((ch2 >> 4) * 16) + (ch2 & 15)) * CHB,
                      sb + SMB + s2 * 8);
        }

        const uint32_t sA = sb + s * STG;
        #pragma unroll
        for (int ks = 0; ks < 4; ks++) {                   // 4 x k16 in the 64-chunk
            uint32_t a[4][4];
            #pragma unroll
            for (int mi = 0; mi < 4; mi++)
                ldsm4(a[mi][0], a[mi][1], a[mi][2], a[mi][3],
                      sA + a_off + mi * (16 * ROWB) + ks * 32);
            uint32_t bf[4][2];
            #pragma unroll
            for (int np = 0; np < 2; np++) {
                uint32_t r0, r1, r2, r3;
                ldsm4(r0, r1, r2, r3, sA + b_off + np * (16 * ROWB) + ks * 32);
                bf[np * 2 + 0][0] = r0; bf[np * 2 + 0][1] = r1;
                bf[np * 2 + 1][0] = r2; bf[np * 2 + 1][1] = r3;
            }
            #pragma unroll
            for (int mi = 0; mi < 4; mi++)
                #pragma unroll
                for (int ni = 0; ni < 4; ni++)
                    mma_f16(acc[mi][ni], a[mi], bf[ni]);
        }

        if (kt == 15) {
            const int c0 = (ch >> 4) << 7;
            #pragma unroll
            for (int ni = 0; ni < 4; ni++) {
                const int cg = c0 + wn * 32 + ni * 8 + tg * 2;
                const float tq0 = __ldg(&g_tq[b * D_ + cg]);
                const float tq1 = __ldg(&g_tq[b * D_ + cg + 1]);
                const float v0  = __ldg(&v[cg]);
                const float v1  = __ldg(&v[cg + 1]);
                #pragma unroll
                for (int mi = 0; mi < 4; mi++) {
                    part[2 * mi]     += tanh_fast(acc[mi][ni][0] + tq0) * v0
                                      + tanh_fast(acc[mi][ni][1] + tq1) * v1;
                    part[2 * mi + 1] += tanh_fast(acc[mi][ni][2] + tq0) * v0
                                      + tanh_fast(acc[mi][ni][3] + tq1) * v1;
                }
            }
        }
        if (++s == 3) s = 0;
    }

    // reduce partials: lanes tg=0..3 hold disjoint cols of same rows
    #pragma unroll
    for (int i = 0; i < 8; i++) {
        float p = part[i];
        p += __shfl_xor_sync(0xFFFFFFFFu, p, 1);
        p += __shfl_xor_sync(0xFFFFFFFFu, p, 2);
        if (tg == 0) {
            int row = wm * 64 + (i >> 1) * 16 + (i & 1) * 8 + gq;
            atomicAdd(&red[row], p);
        }
    }
    __syncthreads();
    if (tid < 128) g_logits[row0 + tid] = red[tid];
}

// ---------------------------------------------------------------------------
// Kernel 3: fused masked softmax + context (reads tiled fp16 M)
// grid (2, 64), 256 threads; softmax recomputed per x-block (cheap).
// ---------------------------------------------------------------------------
__global__ __launch_bounds__(256, 4)
void ctx_softmax(const int* __restrict__ mask, float* __restrict__ out)
{
    __shared__ float ws[N_];
    __shared__ float sred[256];
    const int b = blockIdx.y;
    const int t = threadIdx.x;

    const int   mk0 = mask[b * N_ + t];
    const int   mk1 = mask[b * N_ + t + 256];
    const float l0  = g_logits[b * N_ + t];
    const float l1  = g_logits[b * N_ + t + 256];

    int any = __syncthreads_or(mk0 | mk1);
    if (!any) {                      // whole row masked -> context = 0
        float2 z = {0.f, 0.f};
        ((float2*)(out + b * D_))[blockIdx.x * 256 + t] = z;
        return;
    }
    float x0 = mk0 ? l0 : -1e30f;
    float x1 = mk1 ? l1 : -1e30f;

    sred[t] = fmaxf(x0, x1);
    __syncthreads();
    #pragma unroll
    for (int st = 128; st > 0; st >>= 1) {
        if (t < st) sred[t] = fmaxf(sred[t], sred[t + st]);
        __syncthreads();
    }
    const float mx = sred[0];
    __syncthreads();
    const float e0 = expf(x0 - mx);   // masked lanes underflow to exactly 0
    const float e1 = expf(x1 - mx);
    sred[t] = e0 + e1;
    __syncthreads();
    #pragma unroll
    for (int st = 128; st > 0; st >>= 1) {
        if (t < st) sred[t] += sred[t + st];
        __syncthreads();
    }
    const float inv = 1.f / sred[0];
    ws[t]       = e0 * inv;
    ws[t + 256] = e1 * inv;
    __syncthreads();

    // context: this thread owns fp32 output cols d, d+1
    const int d      = 2 * (blockIdx.x * 256 + t);
    const int kt     = d >> 6;
    const uint32_t off_d = (uint32_t)(((d & 63) >> 3) * 16 + (d & 7) * 2);

    float2 a0 = {0.f, 0.f}, a1 = {0.f, 0.f}, a2 = {0.f, 0.f}, a3 = {0.f, 0.f};
    #pragma unroll
    for (int nb = 0; nb < 4; nb++) {
        const unsigned char* base = g_MhT + (size_t)((b * 4 + nb) * 16 + kt) * CHB + off_d;
        const float* w = ws + nb * 128;
        #pragma unroll 4
        for (int r = 0; r < 128; r += 4) {
            float2 m0 = __half22float2(*(const __half2*)(base + (r + 0) * 144));
            float2 m1 = __half22float2(*(const __half2*)(base + (r + 1) * 144));
            float2 m2 = __half22float2(*(const __half2*)(base + (r + 2) * 144));
            float2 m3 = __half22float2(*(const __half2*)(base + (r + 3) * 144));
            a0.x += w[r + 0] * m0.x; a0.y += w[r + 0] * m0.y;
            a1.x += w[r + 1] * m1.x; a1.y += w[r + 1] * m1.y;
            a2.x += w[r + 2] * m2.x; a2.y += w[r + 2] * m2.y;
            a3.x += w[r + 3] * m3.x; a3.y += w[r + 3] * m3.y;
        }
    }
    float2 rr;
    rr.x = (a0.x + a1.x) + (a2.x + a3.x);
    rr.y = (a0.y + a1.y) + (a2.y + a3.y);
    ((float2*)(out + b * D_))[blockIdx.x * 256 + t] = rr;
}

// ---------------------------------------------------------------------------
extern "C" void kernel_launch(void* const* d_in, const int* in_sizes, int n_in,
                              void* d_out, int out_size)
{
    const float* M     = (const float*)d_in[0];  // (64, 512, 1024)
    const int*   mask  = (const int*)  d_in[1];  // (64, 512)
    const float* query = (const float*)d_in[2];  // (64, 1024)
    const float* Wh    = (const float*)d_in[3];  // (1024, 1024)
    const float* Ws    = (const float*)d_in[4];  // (1024, 1024)
    const float* v     = (const float*)d_in[5];  // (1024, 1)
    float* out = (float*)d_out;                  // (64, 1024)

    cudaFuncSetAttribute(logits_mma, cudaFuncAttributeMaxDynamicSharedMemorySize, SMTOT);

    prep_kernel<<<TQ_BLKS + TRAN_BLKS + CONV_BLKS, 256>>>(M, Wh, query, Ws);
    logits_mma<<<(B_ * N_) / 128, 256, SMTOT>>>(v);
    ctx_softmax<<<dim3(2, B_), 256>>>(mask, out);
}

// round 10
// speedup vs baseline: 7.3775x; 1.0240x over previous
#include <cuda_runtime.h>
#include <cuda_fp16.h>
#include <cstdint>
#include <math.h>

#define B_   64
#define N_   512
#define D_   1024

#define CHB  18432            // one chunk: 128 rows x 144 B (64 halves + 16B pad)
#define RB_  256              // A row-blocks (128 rows each)
#define KT_  16               // K chunks of 64
#define CT_  8                // B column tiles of 128
#define NUNITS 512            // work units: (row-block, col-half)

// Scratch (device globals: no allocation allowed)
__device__ float g_tq[B_ * D_];
__device__ float g_part[2][B_ * N_];   // per-col-half partial logits
__device__ int   g_unit;               // work queue counter (reset in prep)
__device__ __align__(128) unsigned char g_MhT[RB_ * KT_ * CHB];  // tiled fp16 A (72 MB)
__device__ __align__(128) unsigned char g_WhT[CT_ * KT_ * CHB];  // tiled fp16 Wh^T (2.25 MB)

// ---------------------------------------------------------------------------
// helpers
// ---------------------------------------------------------------------------
__device__ __forceinline__ uint32_t smem_u32(const void* p) {
    uint32_t a;
    asm("{ .reg .u64 t; cvta.to.shared.u64 t, %1; cvt.u32.u64 %0, t; }" : "=r"(a) : "l"(p));
    return a;
}
__device__ __forceinline__ float tanh_fast(float x) {
    float t;
    asm("tanh.approx.f32 %0, %1;" : "=f"(t) : "f"(x));
    return t;
}
__device__ __forceinline__ void ldsm4(uint32_t& r0, uint32_t& r1, uint32_t& r2, uint32_t& r3,
                                      uint32_t addr) {
    asm volatile("ldmatrix.sync.aligned.m8n8.x4.shared.b16 {%0,%1,%2,%3}, [%4];"
                 : "=r"(r0), "=r"(r1), "=r"(r2), "=r"(r3) : "r"(addr));
}
__device__ __forceinline__ void mma_f16(float* d, const uint32_t* a, const uint32_t* b) {
    asm volatile("mma.sync.aligned.m16n8k16.row.col.f32.f16.f16.f32 "
                 "{%0,%1,%2,%3}, {%4,%5,%6,%7}, {%8,%9}, {%0,%1,%2,%3};"
                 : "+f"(d[0]), "+f"(d[1]), "+f"(d[2]), "+f"(d[3])
                 : "r"(a[0]), "r"(a[1]), "r"(a[2]), "r"(a[3]), "r"(b[0]), "r"(b[1]));
}
__device__ __forceinline__ void mbar_init(uint32_t mb, uint32_t cnt) {
    asm volatile("mbarrier.init.shared.b64 [%0], %1;" :: "r"(mb), "r"(cnt) : "memory");
}
__device__ __forceinline__ void mbar_wait(uint32_t mb, uint32_t parity) {
    uint32_t done;
    asm volatile(
        "{\n\t.reg .pred p;\n\t"
        "mbarrier.try_wait.parity.acquire.cta.shared::cta.b64 p, [%1], %2;\n\t"
        "selp.b32 %0, 1, 0, p;\n\t}"
        : "=r"(done) : "r"(mb), "r"(parity) : "memory");
    if (!done) {
        asm volatile(
            "{\n\t.reg .pred P1;\n\t"
            "WL_%=:\n\t"
            "mbarrier.try_wait.parity.acquire.cta.shared::cta.b64 P1, [%0], %1, 0x989680;\n\t"
            "@P1 bra.uni WD_%=;\n\t"
            "bra.uni WL_%=;\n\t"
            "WD_%=:\n\t}"
            :: "r"(mb), "r"(parity) : "memory");
    }
}
// issue one chunk: A (18432 B) + B (18432 B) into stage, tracked by one mbarrier
__device__ __forceinline__ void tma_chunk(uint32_t sdst, const void* asrc,
                                          const void* bsrc, uint32_t mbar) {
    asm volatile("mbarrier.arrive.expect_tx.shared.b64 _, [%0], %1;"
                 :: "r"(mbar), "r"(2u * CHB) : "memory");
    asm volatile("cp.async.bulk.shared::cluster.global.mbarrier::complete_tx::bytes "
                 "[%0], [%1], %2, [%3];"
                 :: "r"(sdst), "l"(asrc), "r"((uint32_t)CHB), "r"(mbar) : "memory");
    asm volatile("cp.async.bulk.shared::cluster.global.mbarrier::complete_tx::bytes "
                 "[%0], [%1], %2, [%3];"
                 :: "r"(sdst + CHB), "l"(bsrc), "r"((uint32_t)CHB), "r"(mbar) : "memory");
}

// ---------------------------------------------------------------------------
// Kernel 1 (fused prep): tq = query@Ws (blocks 0..63, first so it overlaps),
// WhT tiled fp16 (next 1024 blocks), M -> tiled fp16 (8192 blocks, 2 units/thr)
// ---------------------------------------------------------------------------
#define TQ_BLKS   64
#define TRAN_BLKS 1024
#define CONV_BLKS 8192
#define HALF_UNITS 2097152u      // 4,194,304 16B-units / 2

__global__ __launch_bounds__(256)
void prep_kernel(const float* __restrict__ M, const float* __restrict__ Wh,
                 const float* __restrict__ query, const float* __restrict__ Ws)
{
    __shared__ float sbuf[2624];
    const int bid = blockIdx.x;
    const int tid = threadIdx.x;

    if (bid < TQ_BLKS) {
        if (bid == 0 && tid == 0) g_unit = 0;    // reset work queue each launch
        // ----- tq = query @ Ws -----
        float (*Qs)[32]  = (float(*)[32])sbuf;          // 16 x 32
        float (*Wss)[64] = (float(*)[64])(sbuf + 512);  // 32 x 64
        const int a_local = tid & 63;
        const int br      = tid >> 6;
        const int a0      = (bid & 15) * 64;
        const int b0      = (bid >> 4) * 16;

        float acc[4] = {0.f, 0.f, 0.f, 0.f};
        for (int k0 = 0; k0 < D_; k0 += 32) {
            #pragma unroll
            for (int i = 0; i < 2; i++) {
                int idx = tid + i * 256;
                Qs[idx >> 5][idx & 31] = query[(b0 + (idx >> 5)) * D_ + k0 + (idx & 31)];
            }
            #pragma unroll
            for (int i = 0; i < 8; i++) {
                int idx = tid + i * 256;
                Wss[idx >> 6][idx & 63] = Ws[(size_t)(k0 + (idx >> 6)) * D_ + a0 + (idx & 63)];
            }
            __syncthreads();
            #pragma unroll
            for (int kk = 0; kk < 32; kk++) {
                float wv = Wss[kk][a_local];
                #pragma unroll
                for (int q = 0; q < 4; q++) acc[q] += Qs[br + q * 4][kk] * wv;
            }
            __syncthreads();
        }
        #pragma unroll
        for (int q = 0; q < 4; q++)
            g_tq[(b0 + br + q * 4) * D_ + a0 + a_local] = acc[q];
    } else if (bid < TQ_BLKS + TRAN_BLKS) {
        // ----- WhT tiled: chunk (ct,kt), row = out-col c, 64 halves of k -----
        const int t  = bid - TQ_BLKS;
        const int kb = t >> 5, cb = t & 31;
        const int k0 = kb * 32, c0 = cb * 32;
        float (*tr)[33] = (float(*)[33])sbuf;
        #pragma unroll
        for (int j = 0; j < 4; j++) {
            int idx = tid + j * 256;
            int i = idx >> 5, x = idx & 31;
            tr[i][x] = Wh[(size_t)(k0 + i) * D_ + c0 + x];
        }
        __syncthreads();
        const int ct = c0 >> 7;
        const int kt = kb >> 1;
        const int hb = (kb & 1) * 32;
        unsigned char* dst = g_WhT + (size_t)(ct * 16 + kt) * CHB;
        #pragma unroll
        for (int j = 0; j < 4; j++) {
            int idx = tid + j * 256;
            int i = idx >> 5, x = idx & 31;
            int rloc = (c0 & 127) + i;
            *(__half*)(dst + rloc * 144 + (hb + x) * 2) = __float2half_rn(tr[x][i]);
        }
    } else {
        // ----- M -> tiled fp16: TWO 16B units per thread (MLP 4) -----
        const uint32_t idx = (uint32_t)(bid - TQ_BLKS - TRAN_BLKS) * 256 + tid;
        #pragma unroll
        for (int half = 0; half < 2; half++) {
            const uint32_t u  = idx + half * HALF_UNITS;
            const uint32_t c  = u & 7;
            const uint32_t r  = (u >> 3) & 127;
            const uint32_t kt = (u >> 10) & 15;
            const uint32_t rb = u >> 14;
            const float4* src = (const float4*)(M + ((size_t)(rb * 128 + r) << 10) + kt * 64 + c * 8);
            float4 x = src[0];
            float4 y = src[1];
            __half2 h0 = __floats2half2_rn(x.x, x.y);
            __half2 h1 = __floats2half2_rn(x.z, x.w);
            __half2 h2 = __floats2half2_rn(y.x, y.y);
            __half2 h3 = __floats2half2_rn(y.z, y.w);
            uint4 o;
            o.x = *(uint32_t*)&h0; o.y = *(uint32_t*)&h1;
            o.z = *(uint32_t*)&h2; o.w = *(uint32_t*)&h3;
            *(uint4*)(g_MhT + (size_t)(rb * 16 + kt) * CHB + r * 144 + c * 16) = o;
        }
    }
}

// ---------------------------------------------------------------------------
// Kernel 2 (dominant): fp16 m16n8k16 mma GEMM + fused tanh·v epilogue
// Persistent 296 CTAs pull 512 units (128 rows x 512 cols) off an atomic
// queue; bulk-async 3-stage mbarrier ring; warp-0-elect waits.
// ---------------------------------------------------------------------------
#define ROWB  144
#define STG   (2 * CHB)           // 36864: A + B for one chunk
#define SRED  (3 * STG)           // 110592
#define SMB   (SRED + 512)        // 3 mbarriers
#define SMU   (SMB + 24)          // unit broadcast slot
#define SMTOT (SMU + 16)

__global__ __launch_bounds__(256, 2)
void logits_mma(const float* __restrict__ v)
{
    extern __shared__ char smem[];
    const uint32_t sb = smem_u32(smem);
    float* red = (float*)(smem + SRED);
    volatile int* su = (volatile int*)(smem + SMU);

    const int tid  = threadIdx.x;
    const int lane = tid & 31;
    const int wid  = tid >> 5;
    const int wm   = wid & 1;          // m block (2 x 64 rows)
    const int wn   = wid >> 1;         // n block (4 x 32 cols)
    const int gq   = lane >> 2;
    const int tg   = lane & 3;

    if (tid == 0) {
        mbar_init(sb + SMB + 0, 1);
        mbar_init(sb + SMB + 8, 1);
        mbar_init(sb + SMB + 16, 1);
        asm volatile("fence.proxy.async.shared::cta;" ::: "memory");
    }
    __syncthreads();

    // ldsm smem offsets within a stage (A at +0, B at +CHB)
    const uint32_t a_off = (uint32_t)((wm * 64 + (lane & 15)) * ROWB + (lane >> 4) * 16);
    const uint32_t b_off = (uint32_t)((wn * 32 + (lane & 7) + ((lane >> 4) & 1) * 8) * ROWB
                                      + ((lane >> 3) & 1) * 16 + CHB);

    uint32_t phases = 0;
    int s = 0;
    float acc[4][4][4];

    for (;;) {
        // ---- grab next unit ----
        if (tid == 0) su[0] = atomicAdd(&g_unit, 1);
        __syncthreads();
        const int u = su[0];
        if (u >= NUNITS) break;

        const int rb   = u >> 1;          // row-block
        const int h    = u & 1;           // col half: c-tiles h*4 .. h*4+3
        const int row0 = rb * 128;
        const int b    = rb >> 2;
        const unsigned char* Abase = g_MhT + (size_t)rb * (KT_ * CHB);
        const unsigned char* Bbase = g_WhT + (size_t)(h * 4 * 16) * CHB;

        if (tid < 128) red[tid] = 0.f;

        float part[8];
        #pragma unroll
        for (int i = 0; i < 8; i++) part[i] = 0.f;

        // prologue: issue chunks 0,1 of this unit into stages s, s+1
        if (tid == 0) {
            int s1 = (s + 1 == 3) ? 0 : s + 1;
            tma_chunk(sb + s * STG,  Abase + 0 * CHB, Bbase + 0 * CHB, sb + SMB + s * 8);
            tma_chunk(sb + s1 * STG, Abase + 1 * CHB, Bbase + 1 * CHB, sb + SMB + s1 * 8);
        }

        for (int ch = 0; ch < 64; ch++) {
            const int kt = ch & 15;
            if (kt == 0) {
                #pragma unroll
                for (int mi = 0; mi < 4; mi++)
                    #pragma unroll
                    for (int ni = 0; ni < 4; ni++)
                        #pragma unroll
                        for (int q = 0; q < 4; q++) acc[mi][ni][q] = 0.f;
            }

            if (wid == 0) mbar_wait(sb + SMB + s * 8, (phases >> s) & 1);
            phases ^= (1u << s);
            __syncthreads();                 // visibility + stage s2 drained

            if (tid == 0 && ch + 2 < 64) {
                const int ch2 = ch + 2;
                int s2 = s + 2; if (s2 >= 3) s2 -= 3;
                tma_chunk(sb + s2 * STG,
                          Abase + (size_t)(ch2 & 15) * CHB,
                          Bbase + (size_t)(((ch2 >> 4) * 16) + (ch2 & 15)) * CHB,
                          sb + SMB + s2 * 8);
            }

            const uint32_t sA = sb + s * STG;
            #pragma unroll
            for (int ks = 0; ks < 4; ks++) {            // 4 x k16 in the 64-chunk
                uint32_t a[4][4];
                #pragma unroll
                for (int mi = 0; mi < 4; mi++)
                    ldsm4(a[mi][0], a[mi][1], a[mi][2], a[mi][3],
                          sA + a_off + mi * (16 * ROWB) + ks * 32);
                uint32_t bf[4][2];
                #pragma unroll
                for (int np = 0; np < 2; np++) {
                    uint32_t r0, r1, r2, r3;
                    ldsm4(r0, r1, r2, r3, sA + b_off + np * (16 * ROWB) + ks * 32);
                    bf[np * 2 + 0][0] = r0; bf[np * 2 + 0][1] = r1;
                    bf[np * 2 + 1][0] = r2; bf[np * 2 + 1][1] = r3;
                }
                #pragma unroll
                for (int mi = 0; mi < 4; mi++)
                    #pragma unroll
                    for (int ni = 0; ni < 4; ni++)
                        mma_f16(acc[mi][ni], a[mi], bf[ni]);
            }

            if (kt == 15) {
                const int c0 = (h * 4 + (ch >> 4)) << 7;
                #pragma unroll
                for (int ni = 0; ni < 4; ni++) {
                    const int cg = c0 + wn * 32 + ni * 8 + tg * 2;
                    const float tq0 = __ldg(&g_tq[b * D_ + cg]);
                    const float tq1 = __ldg(&g_tq[b * D_ + cg + 1]);
                    const float v0  = __ldg(&v[cg]);
                    const float v1  = __ldg(&v[cg + 1]);
                    #pragma unroll
                    for (int mi = 0; mi < 4; mi++) {
                        part[2 * mi]     += tanh_fast(acc[mi][ni][0] + tq0) * v0
                                          + tanh_fast(acc[mi][ni][1] + tq1) * v1;
                        part[2 * mi + 1] += tanh_fast(acc[mi][ni][2] + tq0) * v0
                                          + tanh_fast(acc[mi][ni][3] + tq1) * v1;
                    }
                }
            }
            if (++s == 3) s = 0;
        }

        // reduce partials: lanes tg=0..3 hold disjoint cols of same rows
        #pragma unroll
        for (int i = 0; i < 8; i++) {
            float p = part[i];
            p += __shfl_xor_sync(0xFFFFFFFFu, p, 1);
            p += __shfl_xor_sync(0xFFFFFFFFu, p, 2);
            if (tg == 0) {
                int row = wm * 64 + (i >> 1) * 16 + (i & 1) * 8 + gq;
                atomicAdd(&red[row], p);
            }
        }
        __syncthreads();
        if (tid < 128) g_part[h][row0 + tid] = red[tid];
        // next unit's broadcast __syncthreads orders red reuse
    }
}

// ---------------------------------------------------------------------------
// Kernel 3: fused masked softmax + context (reads tiled fp16 M)
// grid (2, 64), 256 threads; softmax recomputed per x-block (cheap).
// ---------------------------------------------------------------------------
__global__ __launch_bounds__(256, 4)
void ctx_softmax(const int* __restrict__ mask, float* __restrict__ out)
{
    __shared__ float ws[N_];
    __shared__ float sred[256];
    const int b = blockIdx.y;
    const int t = threadIdx.x;

    const int   mk0 = mask[b * N_ + t];
    const int   mk1 = mask[b * N_ + t + 256];
    const float l0  = g_part[0][b * N_ + t] + g_part[1][b * N_ + t];
    const float l1  = g_part[0][b * N_ + t + 256] + g_part[1][b * N_ + t + 256];

    int any = __syncthreads_or(mk0 | mk1);
    if (!any) {                      // whole row masked -> context = 0
        float2 z = {0.f, 0.f};
        ((float2*)(out + b * D_))[blockIdx.x * 256 + t] = z;
        return;
    }
    float x0 = mk0 ? l0 : -1e30f;
    float x1 = mk1 ? l1 : -1e30f;

    sred[t] = fmaxf(x0, x1);
    __syncthreads();
    #pragma unroll
    for (int st = 128; st > 0; st >>= 1) {
        if (t < st) sred[t] = fmaxf(sred[t], sred[t + st]);
        __syncthreads();
    }
    const float mx = sred[0];
    __syncthreads();
    const float e0 = expf(x0 - mx);   // masked lanes underflow to exactly 0
    const float e1 = expf(x1 - mx);
    sred[t] = e0 + e1;
    __syncthreads();
    #pragma unroll
    for (int st = 128; st > 0; st >>= 1) {
        if (t < st) sred[t] += sred[t + st];
        __syncthreads();
    }
    const float inv = 1.f / sred[0];
    ws[t]       = e0 * inv;
    ws[t + 256] = e1 * inv;
    __syncthreads();

    // context: this thread owns fp32 output cols d, d+1
    const int d      = 2 * (blockIdx.x * 256 + t);
    const int kt     = d >> 6;
    const uint32_t off_d = (uint32_t)(((d & 63) >> 3) * 16 + (d & 7) * 2);

    float2 a0 = {0.f, 0.f}, a1 = {0.f, 0.f}, a2 = {0.f, 0.f}, a3 = {0.f, 0.f};
    #pragma unroll
    for (int nb = 0; nb < 4; nb++) {
        const unsigned char* base = g_MhT + (size_t)((b * 4 + nb) * 16 + kt) * CHB + off_d;
        const float* w = ws + nb * 128;
        #pragma unroll 4
        for (int r = 0; r < 128; r += 4) {
            float2 m0 = __half22float2(*(const __half2*)(base + (r + 0) * 144));
            float2 m1 = __half22float2(*(const __half2*)(base + (r + 1) * 144));
            float2 m2 = __half22float2(*(const __half2*)(base + (r + 2) * 144));
            float2 m3 = __half22float2(*(const __half2*)(base + (r + 3) * 144));
            a0.x += w[r + 0] * m0.x; a0.y += w[r + 0] * m0.y;
            a1.x += w[r + 1] * m1.x; a1.y += w[r + 1] * m1.y;
            a2.x += w[r + 2] * m2.x; a2.y += w[r + 2] * m2.y;
            a3.x += w[r + 3] * m3.x; a3.y += w[r + 3] * m3.y;
        }
    }
    float2 rr;
    rr.x = (a0.x + a1.x) + (a2.x + a3.x);
    rr.y = (a0.y + a1.y) + (a2.y + a3.y);
    ((float2*)(out + b * D_))[blockIdx.x * 256 + t] = rr;
}

// ---------------------------------------------------------------------------
extern "C" void kernel_launch(void* const* d_in, const int* in_sizes, int n_in,
                              void* d_out, int out_size)
{
    const float* M     = (const float*)d_in[0];  // (64, 512, 1024)
    const int*   mask  = (const int*)  d_in[1];  // (64, 512)
    const float* query = (const float*)d_in[2];  // (64, 1024)
    const float* Wh    = (const float*)d_in[3];  // (1024, 1024)
    const float* Ws    = (const float*)d_in[4];  // (1024, 1024)
    const float* v     = (const float*)d_in[5];  // (1024, 1)
    float* out = (float*)d_out;                  // (64, 1024)

    cudaFuncSetAttribute(logits_mma, cudaFuncAttributeMaxDynamicSharedMemorySize, SMTOT);

    prep_kernel<<<TQ_BLKS + TRAN_BLKS + CONV_BLKS, 256>>>(M, Wh, query, Ws);
    logits_mma<<<296, 256, SMTOT>>>(v);
    ctx_softmax<<<dim3(2, B_), 256>>>(mask, out);
}